// round 6
// baseline (speedup 1.0000x reference)
#include <cuda_runtime.h>
#include <cstdint>

#define NB 32
#define NIMG 640
#define CH 50176
#define IMG_SZ 150528

__device__ float g_backbone[2 * NIMG * 6];

// dynamic smem layout (floats)
#define O_BUF    0        // 2 x 4032 strip buffers (6 rows x 224 x 3ch, 16128 B each)
#define O_CARRY  8064     // 672: 1 carry row x 224 x 3ch
#define O_CONV   8736     // 1008: conv1 rows [3oc][3j][112]; reused in stage2
#define O_POOL1  9744     // 4107: [3][37][37]
#define O_W2     13852
#define O_B1     13880
#define O_B2     13883
#define O_LW     13884
#define O_LB     14100
#define O_MBAR   14106    // 2 x u64 mbarriers (8B aligned: 14106*4 = 56424)
#define SMEM_FLOATS 14112
#define SMEM_BYTES  (SMEM_FLOATS * 4)   // 56448 B -> 4 blocks/SM

#define STRIP_BYTES 16128   // 3 * 6 * 224 * 4
#define CH_STRIP_B  5376    // 6 * 224 * 4
#define CARRY_BYTES 2688    // 3 * 224 * 4

__device__ __forceinline__ uint32_t s2u(const void* p) {
    uint32_t a;
    asm("{ .reg .u64 t; cvta.to.shared.u64 t, %1; cvt.u32.u64 %0, t; }" : "=r"(a) : "l"(p));
    return a;
}
__device__ __forceinline__ void mbar_init(uint32_t a, uint32_t cnt) {
    asm volatile("mbarrier.init.shared.b64 [%0], %1;" :: "r"(a), "r"(cnt) : "memory");
}
__device__ __forceinline__ void mbar_expect(uint32_t a, uint32_t tx) {
    asm volatile("mbarrier.arrive.expect_tx.shared.b64 _, [%0], %1;" :: "r"(a), "r"(tx) : "memory");
}
__device__ __forceinline__ void mbar_wait(uint32_t a, uint32_t par) {
    asm volatile(
        "{\n\t.reg .pred P;\n"
        "WL%=:\n\t"
        "mbarrier.try_wait.parity.acquire.cta.shared::cta.b64 P, [%0], %1, 0x989680;\n\t"
        "@!P bra WL%=;\n\t}"
        :: "r"(a), "r"(par) : "memory");
}
__device__ __forceinline__ void bulk_g2s(uint32_t dst, const float* src,
                                         uint32_t bytes, uint32_t mbar) {
    asm volatile(
        "cp.async.bulk.shared::cluster.global.mbarrier::complete_tx::bytes "
        "[%0], [%1], %2, [%3];"
        :: "r"(dst), "l"(src), "r"(bytes), "r"(mbar) : "memory");
}
__device__ __forceinline__ void l2_prefetch(const float* p) {
    asm volatile("prefetch.global.L2 [%0];" :: "l"(p));
}

// strip pr = image rows [6*pr+1, 6*pr+7), 6 rows x 3 channels
__device__ __forceinline__ void issue_strip(uint32_t bufb, int buf, const float* in,
                                            int pr, uint32_t mbar) {
    mbar_expect(mbar, STRIP_BYTES);
    uint32_t dst = bufb + (uint32_t)buf * STRIP_BYTES;
    const float* src = in + (6 * pr + 1) * 224;
    #pragma unroll
    for (int ic = 0; ic < 3; ic++)
        bulk_g2s(dst + ic * CH_STRIP_B, src + ic * CH, CH_STRIP_B, mbar);
}

__global__ __launch_bounds__(128, 4)
void backbone_kernel(const float* __restrict__ nodes,
                     const float* __restrict__ depths,
                     const float* __restrict__ c1w,  const float* __restrict__ c1b,
                     const float* __restrict__ c2w,  const float* __restrict__ c2b,
                     const float* __restrict__ lw,   const float* __restrict__ lb,
                     const float* __restrict__ dc1w, const float* __restrict__ dc1b,
                     const float* __restrict__ dc2w, const float* __restrict__ dc2b,
                     const float* __restrict__ dlw,  const float* __restrict__ dlb)
{
    extern __shared__ float sm[];
    const int img = blockIdx.x;
    const int bb  = blockIdx.y;
    const int tid = threadIdx.x;

    const float* in  = (bb == 0 ? nodes : depths) + (size_t)img * IMG_SZ;
    const float* w1  = bb == 0 ? c1w : dc1w;
    const float* b1  = bb == 0 ? c1b : dc1b;
    const float* w2  = bb == 0 ? c2w : dc2w;
    const float* b2  = bb == 0 ? c2b : dc2b;
    const float* lwp = bb == 0 ? lw  : dlw;
    const float* lbp = bb == 0 ? lb  : dlb;

    const uint32_t bufb   = s2u(sm + O_BUF);
    const uint32_t carryb = s2u(sm + O_CARRY);
    const uint32_t mb0    = s2u(sm + O_MBAR);
    const uint32_t mb1    = mb0 + 8;

    float W[81];
    #pragma unroll
    for (int i = 0; i < 81; i++) W[i] = __ldg(w1 + i);

    if (tid < 27) sm[O_W2 + tid] = w2[tid];
    if (tid < 3)  sm[O_B1 + tid] = b1[tid];
    if (tid == 0) sm[O_B2] = b2[0];
    for (int t = tid; t < 216; t += 128) sm[O_LW + t] = lwp[t];
    if (tid < 6)  sm[O_LB + tid] = lbp[tid];

    if (tid == 0) {
        mbar_init(mb0, 1);
        mbar_init(mb1, 1);
        asm volatile("fence.proxy.async.shared::cta;" ::: "memory");
    }
    __syncthreads();

    // prologue: carry = image row 0 (all ch) + strips 0, 1
    if (tid == 0) {
        mbar_expect(mb0, STRIP_BYTES + CARRY_BYTES);
        #pragma unroll
        for (int ic = 0; ic < 3; ic++)
            bulk_g2s(carryb + ic * 896, in + ic * CH, 896, mb0);
        const float* s0 = in + 224;
        #pragma unroll
        for (int ic = 0; ic < 3; ic++)
            bulk_g2s(bufb + ic * CH_STRIP_B, s0 + ic * CH, CH_STRIP_B, mb0);
        issue_strip(bufb, 1, in, 1, mb1);
    }

    for (int pr = 0; pr < 37; pr++) {
        const int b = pr & 1;
        mbar_wait(b ? mb1 : mb0, (pr >> 1) & 1);   // strip pr (+carry at pr=0)

        // ---- conv1: 111 cols x 3 conv rows x 3 oc -------------------------
        // input row r: r=0 -> carry (image row 6*pr), r=1..6 -> strip rows
        if (tid < 111) {
            const int x = tid;
            float a[3][3] = {{0.f,0.f,0.f},{0.f,0.f,0.f},{0.f,0.f,0.f}};
            #pragma unroll
            for (int ic = 0; ic < 3; ic++) {
                const float* cp = sm + O_CARRY + ic * 224 + 2 * x;
                const float* bp = sm + O_BUF + b * 4032 + ic * 1344 + 2 * x;
                #pragma unroll
                for (int r = 0; r < 7; r++) {
                    const float* rp = (r == 0) ? cp : bp + (r - 1) * 224;
                    float2 p = *reinterpret_cast<const float2*>(rp);
                    float  q = rp[2];
                    #pragma unroll
                    for (int j = 0; j < 3; j++) {
                        const int ky = r - 2 * j;
                        if (ky >= 0 && ky < 3) {
                            #pragma unroll
                            for (int oc = 0; oc < 3; oc++) {
                                const int wb = (oc * 3 + ic) * 9 + ky * 3;
                                a[j][oc] = fmaf(p.x, W[wb],
                                           fmaf(p.y, W[wb + 1],
                                           fmaf(q,   W[wb + 2], a[j][oc])));
                            }
                        }
                    }
                }
            }
            #pragma unroll
            for (int j = 0; j < 3; j++)
                #pragma unroll
                for (int oc = 0; oc < 3; oc++)
                    sm[O_CONV + (oc * 3 + j) * 112 + x] = a[j][oc];
        }
        __syncthreads();   // conv reads of carry + buf[b] done

        // carry <- last row of strip pr (image row 6*pr+6); 168 float4
        for (int q = tid; q < 168; q += 128) {
            int ic = q / 56, x4 = q % 56;
            *reinterpret_cast<float4*>(&sm[O_CARRY + ic * 224 + x4 * 4]) =
                *reinterpret_cast<const float4*>(
                    &sm[O_BUF + b * 4032 + ic * 1344 + 5 * 224 + x4 * 4]);
        }

        // ---- pool1 + bias + relu -----------------------------------------
        if (tid < 111) {
            const int oc = tid / 37, px = tid % 37;
            float m = -1e30f;
            #pragma unroll
            for (int j = 0; j < 3; j++)
                #pragma unroll
                for (int i = 0; i < 3; i++)
                    m = fmaxf(m, sm[O_CONV + (oc * 3 + j) * 112 + 3 * px + i]);
            sm[O_POOL1 + (oc * 37 + pr) * 37 + px] = fmaxf(m + sm[O_B1 + oc], 0.f);
        }
        __syncthreads();   // carry copy + buf[b] reads retired -> safe to refill

        if (tid == 0 && pr + 2 < 37)
            issue_strip(bufb, b, in, pr + 2, b ? mb1 : mb0);
    }
    __syncthreads();

    // ---- stage 2: conv2 -> pool2 -> relu -> linear 36->6 -------------------
    for (int t2 = tid; t2 < 324; t2 += 128) {
        int cy = t2 / 18, cx = t2 % 18;
        float acc = 0.f;
        #pragma unroll
        for (int ic = 0; ic < 3; ic++)
            #pragma unroll
            for (int ky = 0; ky < 3; ky++)
                #pragma unroll
                for (int kx = 0; kx < 3; kx++)
                    acc = fmaf(sm[O_W2 + (ic * 3 + ky) * 3 + kx],
                               sm[O_POOL1 + (ic * 37 + 2 * cy + ky) * 37 + 2 * cx + kx],
                               acc);
        sm[O_CONV + t2] = acc;
    }
    __syncthreads();

    if (tid < 36) {
        int py = tid / 6, px = tid % 6;
        float m = -1e30f;
        #pragma unroll
        for (int i = 0; i < 3; i++)
            #pragma unroll
            for (int j = 0; j < 3; j++)
                m = fmaxf(m, sm[O_CONV + (3 * py + i) * 18 + 3 * px + j]);
        sm[O_CONV + 400 + tid] = fmaxf(m + sm[O_B2], 0.f);
    }
    __syncthreads();

    if (tid < 6) {
        float acc = sm[O_LB + tid];
        #pragma unroll
        for (int i = 0; i < 36; i++)
            acc = fmaf(sm[O_CONV + 400 + i], sm[O_LW + i * 6 + tid], acc);
        g_backbone[bb * (NIMG * 6) + img * 6 + tid] = acc;
    }
}

// ---------------------------------------------------------------------------
// Head: 768 threads/block, one block per sample (unchanged from R5).
// ---------------------------------------------------------------------------
__global__ __launch_bounds__(768)
void head_kernel(const float* __restrict__ pos,  const float* __restrict__ attmap,
                 const float* __restrict__ fmw,  const float* __restrict__ fmb,
                 const float* __restrict__ lmw,  const float* __restrict__ lmb,
                 const float* __restrict__ o1w,  const float* __restrict__ o1b,
                 const float* __restrict__ o2w,  const float* __restrict__ o2b,
                 const float* __restrict__ o3w,  const float* __restrict__ o3b,
                 float* __restrict__ out)
{
    const int bx = blockIdx.x;
    const int t  = threadIdx.x;

    __shared__ float feat[360];
    __shared__ float h1p[4][180], h1[180];
    __shared__ float h2p[4][60],  h2[60];
    __shared__ float h3p[6][6];

    {
        for (int i = t; i < 2025; i += 768) l2_prefetch(o1w + i * 32);
        for (int i = t; i < 338;  i += 768) l2_prefetch(o2w + i * 32);
        if (t < 12) l2_prefetch(o3w + t * 32);
    }

    if (t < 120) {
        int f = t / 24, m = (t % 24) / 6, d = t % 6;
        int fm = f * 4 + m;
        int gi = ((bx * 5 + f) * 4 + m) * 6 + d;
        feat[fm * 18 + d]     = g_backbone[gi];
        feat[fm * 18 + 6 + d] = g_backbone[NIMG * 6 + gi];
    } else if (t >= 384 && t < 504) {
        int tt = t - 384;
        int f = tt / 24, n = (tt % 24) / 6, d = tt % 6;
        const float* pb = pos    + bx * 120;
        const float* ab = attmap + bx * 80;
        float acc = 0.f;
        #pragma unroll
        for (int m = 0; m < 4; m++) {
            float pm = __ldg(fmb + d);
            #pragma unroll
            for (int e = 0; e < 6; e++)
                pm = fmaf(__ldg(pb + f * 24 + m * 6 + e), __ldg(fmw + e * 6 + d), pm);
            acc = fmaf(__ldg(ab + f * 16 + m * 4 + n), pm, acc);
        }
        if (f >= 1) {
            float pv = __ldg(lmb + d);
            #pragma unroll
            for (int e = 0; e < 6; e++)
                pv = fmaf(__ldg(pb + (f - 1) * 24 + n * 6 + e), __ldg(lmw + e * 6 + d), pv);
            acc += pv;
        }
        feat[(f * 4 + n) * 18 + 12 + d] = acc;
    }
    __syncthreads();

    if (t < 720) {
        int q = t / 180, o = t - q * 180;
        int base = q * 90;
        const float* wp = o1w + base * 180 + o;
        float a = 0.f;
        #pragma unroll 15
        for (int i = 0; i < 90; i++)
            a = fmaf(feat[base + i], wp[i * 180], a);
        h1p[q][o] = a;
    }
    __syncthreads();
    if (t < 180)
        h1[t] = fmaxf(h1p[0][t] + h1p[1][t] + h1p[2][t] + h1p[3][t] + o1b[t], 0.f);
    __syncthreads();

    if (t < 240) {
        int q = t / 60, o = t - q * 60;
        int base = q * 45;
        const float* wp = o2w + base * 60 + o;
        float a = 0.f;
        #pragma unroll 15
        for (int i = 0; i < 45; i++)
            a = fmaf(h1[base + i], wp[i * 60], a);
        h2p[q][o] = a;
    }
    __syncthreads();
    if (t < 60)
        h2[t] = fmaxf(h2p[0][t] + h2p[1][t] + h2p[2][t] + h2p[3][t] + o2b[t], 0.f);
    __syncthreads();

    if (t < 36) {
        int q = t / 6, o = t - q * 6;
        int base = q * 10;
        float a = 0.f;
        #pragma unroll
        for (int i = 0; i < 10; i++)
            a = fmaf(h2[base + i], __ldg(o3w + (base + i) * 6 + o), a);
        h3p[q][o] = a;
    }
    __syncthreads();
    if (t < 6) {
        float a = o3b[t];
        #pragma unroll
        for (int q = 0; q < 6; q++) a += h3p[q][t];
        out[bx * 6 + t] = a;
    }
}

extern "C" void kernel_launch(void* const* d_in, const int* in_sizes, int n_in,
                              void* d_out, int out_size)
{
    const float* nodes  = (const float*)d_in[0];
    const float* pos    = (const float*)d_in[1];
    const float* attmap = (const float*)d_in[2];
    const float* depths = (const float*)d_in[3];
    const float* c1w  = (const float*)d_in[4];
    const float* c1b  = (const float*)d_in[5];
    const float* c2w  = (const float*)d_in[6];
    const float* c2b  = (const float*)d_in[7];
    const float* lw   = (const float*)d_in[8];
    const float* lb   = (const float*)d_in[9];
    const float* dc1w = (const float*)d_in[10];
    const float* dc1b = (const float*)d_in[11];
    const float* dc2w = (const float*)d_in[12];
    const float* dc2b = (const float*)d_in[13];
    const float* dlw  = (const float*)d_in[14];
    const float* dlb  = (const float*)d_in[15];
    const float* fmw  = (const float*)d_in[16];
    const float* fmb  = (const float*)d_in[17];
    const float* lmw  = (const float*)d_in[18];
    const float* lmb  = (const float*)d_in[19];
    const float* o1w  = (const float*)d_in[20];
    const float* o1b  = (const float*)d_in[21];
    const float* o2w  = (const float*)d_in[22];
    const float* o2b  = (const float*)d_in[23];
    const float* o3w  = (const float*)d_in[24];
    const float* o3b  = (const float*)d_in[25];

    cudaFuncSetAttribute(backbone_kernel,
                         cudaFuncAttributeMaxDynamicSharedMemorySize, SMEM_BYTES);

    backbone_kernel<<<dim3(NIMG, 2), 128, SMEM_BYTES>>>(
        nodes, depths, c1w, c1b, c2w, c2b, lw, lb,
        dc1w, dc1b, dc2w, dc2b, dlw, dlb);
    head_kernel<<<NB, 768>>>(pos, attmap, fmw, fmb, lmw, lmb,
                             o1w, o1b, o2w, o2b, o3w, o3b,
                             (float*)d_out);
}

// round 7
// speedup vs baseline: 1.1121x; 1.1121x over previous
#include <cuda_runtime.h>
#include <cstdint>

#define NB 32
#define NIMG 640
#define CH 50176
#define IMG_SZ 150528

__device__ float g_backbone[2 * NIMG * 6];

// dynamic smem layout (floats)
#define O_BUF    0        // 2 x 4704 strip buffers (18816 B each)
#define O_CONV   9408     // 2 x 1008: double-buffered conv1 rows [3oc][3j][112]
#define O_POOL1  11424    // 4107: [3][37][37]
#define O_W2     15532
#define O_B1     15560
#define O_B2     15563
#define O_LW     15564
#define O_LB     15780
#define O_MBAR   15786    // 2 x u64 mbarriers (15786*4 = 63144, 8B aligned)
#define SMEM_FLOATS 15790
#define SMEM_BYTES  (SMEM_FLOATS * 4)   // 63160 B -> 3 blocks/SM

#define STRIP_BYTES 18816   // 3 * 7 * 224 * 4

__device__ __forceinline__ uint32_t s2u(const void* p) {
    uint32_t a;
    asm("{ .reg .u64 t; cvta.to.shared.u64 t, %1; cvt.u32.u64 %0, t; }" : "=r"(a) : "l"(p));
    return a;
}
__device__ __forceinline__ void mbar_init(uint32_t a, uint32_t cnt) {
    asm volatile("mbarrier.init.shared.b64 [%0], %1;" :: "r"(a), "r"(cnt) : "memory");
}
__device__ __forceinline__ void mbar_expect(uint32_t a, uint32_t tx) {
    asm volatile("mbarrier.arrive.expect_tx.shared.b64 _, [%0], %1;" :: "r"(a), "r"(tx) : "memory");
}
__device__ __forceinline__ void mbar_wait(uint32_t a, uint32_t par) {
    asm volatile(
        "{\n\t.reg .pred P;\n"
        "WL%=:\n\t"
        "mbarrier.try_wait.parity.acquire.cta.shared::cta.b64 P, [%0], %1, 0x989680;\n\t"
        "@!P bra WL%=;\n\t}"
        :: "r"(a), "r"(par) : "memory");
}
__device__ __forceinline__ void bulk_g2s(uint32_t dst, const float* src,
                                         uint32_t bytes, uint32_t mbar) {
    asm volatile(
        "cp.async.bulk.shared::cluster.global.mbarrier::complete_tx::bytes "
        "[%0], [%1], %2, [%3];"
        :: "r"(dst), "l"(src), "r"(bytes), "r"(mbar) : "memory");
}
__device__ __forceinline__ void l2_prefetch(const float* p) {
    asm volatile("prefetch.global.L2 [%0];" :: "l"(p));
}

// strip pr = image rows [6*pr, 6*pr+7), 7 rows x 3 channels
__device__ __forceinline__ void issue_strip(uint32_t bufb, int buf, const float* src,
                                            uint32_t mbar) {
    mbar_expect(mbar, STRIP_BYTES);
    uint32_t dst = bufb + (uint32_t)buf * STRIP_BYTES;
    #pragma unroll
    for (int ic = 0; ic < 3; ic++)
        bulk_g2s(dst + ic * 6272, src + ic * CH, 6272, mbar);
}

__global__ __launch_bounds__(128)
void backbone_kernel(const float* __restrict__ nodes,
                     const float* __restrict__ depths,
                     const float* __restrict__ c1w,  const float* __restrict__ c1b,
                     const float* __restrict__ c2w,  const float* __restrict__ c2b,
                     const float* __restrict__ lw,   const float* __restrict__ lb,
                     const float* __restrict__ dc1w, const float* __restrict__ dc1b,
                     const float* __restrict__ dc2w, const float* __restrict__ dc2b,
                     const float* __restrict__ dlw,  const float* __restrict__ dlb)
{
    extern __shared__ float sm[];
    const int img = blockIdx.x;
    const int bb  = blockIdx.y;
    const int tid = threadIdx.x;

    const float* in  = (bb == 0 ? nodes : depths) + (size_t)img * IMG_SZ;
    const float* w1  = bb == 0 ? c1w : dc1w;
    const float* b1  = bb == 0 ? c1b : dc1b;
    const float* w2  = bb == 0 ? c2w : dc2w;
    const float* b2  = bb == 0 ? c2b : dc2b;
    const float* lwp = bb == 0 ? lw  : dlw;
    const float* lbp = bb == 0 ? lb  : dlb;

    const uint32_t bufb = s2u(sm + O_BUF);
    const uint32_t mb0  = s2u(sm + O_MBAR);
    const uint32_t mb1  = mb0 + 8;

    float W[81];
    #pragma unroll
    for (int i = 0; i < 81; i++) W[i] = __ldg(w1 + i);

    if (tid < 27) sm[O_W2 + tid] = w2[tid];
    if (tid < 3)  sm[O_B1 + tid] = b1[tid];
    if (tid == 0) sm[O_B2] = b2[0];
    for (int t = tid; t < 216; t += 128) sm[O_LW + t] = lwp[t];
    if (tid < 6)  sm[O_LB + tid] = lbp[tid];

    if (tid == 0) {
        mbar_init(mb0, 1);
        mbar_init(mb1, 1);
        asm volatile("fence.proxy.async.shared::cta;" ::: "memory");
    }
    __syncthreads();

    if (tid == 0) {
        issue_strip(bufb, 0, in, mb0);
        issue_strip(bufb, 1, in + 6 * 224, mb1);
    }

    // single barrier per strip; conv scratch double-buffered on strip parity
    for (int pr = 0; pr < 37; pr++) {
        const int b = pr & 1;
        mbar_wait(b ? mb1 : mb0, (pr >> 1) & 1);

        if (tid < 111) {
            const int x = tid;
            float a[3][3] = {{0.f,0.f,0.f},{0.f,0.f,0.f},{0.f,0.f,0.f}};
            #pragma unroll
            for (int ic = 0; ic < 3; ic++) {
                const float* rp = sm + O_BUF + b * 4704 + ic * 1568 + 2 * x;
                #pragma unroll
                for (int r = 0; r < 7; r++) {
                    float2 p = *reinterpret_cast<const float2*>(rp + r * 224);
                    float  q = rp[r * 224 + 2];
                    #pragma unroll
                    for (int j = 0; j < 3; j++) {
                        const int ky = r - 2 * j;
                        if (ky >= 0 && ky < 3) {
                            #pragma unroll
                            for (int oc = 0; oc < 3; oc++) {
                                const int wb = (oc * 3 + ic) * 9 + ky * 3;
                                a[j][oc] = fmaf(p.x, W[wb],
                                           fmaf(p.y, W[wb + 1],
                                           fmaf(q,   W[wb + 2], a[j][oc])));
                            }
                        }
                    }
                }
            }
            #pragma unroll
            for (int j = 0; j < 3; j++)
                #pragma unroll
                for (int oc = 0; oc < 3; oc++)
                    sm[O_CONV + b * 1008 + (oc * 3 + j) * 112 + x] = a[j][oc];
        }
        __syncthreads();   // conv writes visible; conv reads of buf[b] retired

        if (tid == 0 && pr + 2 < 37)
            issue_strip(bufb, b, in + 6 * (pr + 2) * 224, b ? mb1 : mb0);

        if (tid < 111) {
            const int oc = tid / 37, px = tid % 37;
            float m = -1e30f;
            #pragma unroll
            for (int j = 0; j < 3; j++)
                #pragma unroll
                for (int i = 0; i < 3; i++)
                    m = fmaxf(m, sm[O_CONV + b * 1008 + (oc * 3 + j) * 112 + 3 * px + i]);
            sm[O_POOL1 + (oc * 37 + pr) * 37 + px] = fmaxf(m + sm[O_B1 + oc], 0.f);
        }
        // no trailing barrier: next iteration writes the OTHER conv buffer,
        // and the next __syncthreads orders pool(pr) before conv(pr+2).
    }
    __syncthreads();

    for (int t2 = tid; t2 < 324; t2 += 128) {
        int cy = t2 / 18, cx = t2 % 18;
        float acc = 0.f;
        #pragma unroll
        for (int ic = 0; ic < 3; ic++)
            #pragma unroll
            for (int ky = 0; ky < 3; ky++)
                #pragma unroll
                for (int kx = 0; kx < 3; kx++)
                    acc = fmaf(sm[O_W2 + (ic * 3 + ky) * 3 + kx],
                               sm[O_POOL1 + (ic * 37 + 2 * cy + ky) * 37 + 2 * cx + kx],
                               acc);
        sm[O_CONV + t2] = acc;
    }
    __syncthreads();

    if (tid < 36) {
        int py = tid / 6, px = tid % 6;
        float m = -1e30f;
        #pragma unroll
        for (int i = 0; i < 3; i++)
            #pragma unroll
            for (int j = 0; j < 3; j++)
                m = fmaxf(m, sm[O_CONV + (3 * py + i) * 18 + 3 * px + j]);
        sm[O_CONV + 400 + tid] = fmaxf(m + sm[O_B2], 0.f);
    }
    __syncthreads();

    if (tid < 6) {
        float acc = sm[O_LB + tid];
        #pragma unroll
        for (int i = 0; i < 36; i++)
            acc = fmaf(sm[O_CONV + 400 + i], sm[O_LW + i * 6 + tid], acc);
        g_backbone[bb * (NIMG * 6) + img * 6 + tid] = acc;
    }
}

// ---------------------------------------------------------------------------
// Head with PDL: launches while backbone is still running; prefetches weights
// and computes the backbone-independent message passing, THEN waits on the
// grid dependency before reading g_backbone.
// ---------------------------------------------------------------------------
__global__ __launch_bounds__(768)
void head_kernel(const float* __restrict__ pos,  const float* __restrict__ attmap,
                 const float* __restrict__ fmw,  const float* __restrict__ fmb,
                 const float* __restrict__ lmw,  const float* __restrict__ lmb,
                 const float* __restrict__ o1w,  const float* __restrict__ o1b,
                 const float* __restrict__ o2w,  const float* __restrict__ o2b,
                 const float* __restrict__ o3w,  const float* __restrict__ o3b,
                 float* __restrict__ out)
{
    const int bx = blockIdx.x;
    const int t  = threadIdx.x;

    __shared__ float feat[360];
    __shared__ float h1p[4][180], h1[180];
    __shared__ float h2p[4][60],  h2[60];
    __shared__ float h3p[6][6];

    // (1) data-independent: L2 prefetch of MLP weights
    for (int i = t; i < 2025; i += 768) l2_prefetch(o1w + i * 32);
    for (int i = t; i < 338;  i += 768) l2_prefetch(o2w + i * 32);
    if (t < 12) l2_prefetch(o3w + t * 32);

    // (2) backbone-independent: message passing from pos/attmap
    if (t >= 384 && t < 504) {
        int tt = t - 384;
        int f = tt / 24, n = (tt % 24) / 6, d = tt % 6;
        const float* pb = pos    + bx * 120;
        const float* ab = attmap + bx * 80;
        float acc = 0.f;
        #pragma unroll
        for (int m = 0; m < 4; m++) {
            float pm = __ldg(fmb + d);
            #pragma unroll
            for (int e = 0; e < 6; e++)
                pm = fmaf(__ldg(pb + f * 24 + m * 6 + e), __ldg(fmw + e * 6 + d), pm);
            acc = fmaf(__ldg(ab + f * 16 + m * 4 + n), pm, acc);
        }
        if (f >= 1) {
            float pv = __ldg(lmb + d);
            #pragma unroll
            for (int e = 0; e < 6; e++)
                pv = fmaf(__ldg(pb + (f - 1) * 24 + n * 6 + e), __ldg(lmw + e * 6 + d), pv);
            acc += pv;
        }
        feat[(f * 4 + n) * 18 + 12 + d] = acc;
    }

    // (3) wait for backbone grid to complete (no-op if PDL not active)
    asm volatile("griddepcontrol.wait;" ::: "memory");

    if (t < 120) {
        int f = t / 24, m = (t % 24) / 6, d = t % 6;
        int fm = f * 4 + m;
        int gi = ((bx * 5 + f) * 4 + m) * 6 + d;
        feat[fm * 18 + d]     = g_backbone[gi];
        feat[fm * 18 + 6 + d] = g_backbone[NIMG * 6 + gi];
    }
    __syncthreads();

    if (t < 720) {
        int q = t / 180, o = t - q * 180;
        int base = q * 90;
        const float* wp = o1w + base * 180 + o;
        float a = 0.f;
        #pragma unroll 15
        for (int i = 0; i < 90; i++)
            a = fmaf(feat[base + i], wp[i * 180], a);
        h1p[q][o] = a;
    }
    __syncthreads();
    if (t < 180)
        h1[t] = fmaxf(h1p[0][t] + h1p[1][t] + h1p[2][t] + h1p[3][t] + o1b[t], 0.f);
    __syncthreads();

    if (t < 240) {
        int q = t / 60, o = t - q * 60;
        int base = q * 45;
        const float* wp = o2w + base * 60 + o;
        float a = 0.f;
        #pragma unroll 15
        for (int i = 0; i < 45; i++)
            a = fmaf(h1[base + i], wp[i * 60], a);
        h2p[q][o] = a;
    }
    __syncthreads();
    if (t < 60)
        h2[t] = fmaxf(h2p[0][t] + h2p[1][t] + h2p[2][t] + h2p[3][t] + o2b[t], 0.f);
    __syncthreads();

    if (t < 36) {
        int q = t / 6, o = t - q * 6;
        int base = q * 10;
        float a = 0.f;
        #pragma unroll
        for (int i = 0; i < 10; i++)
            a = fmaf(h2[base + i], __ldg(o3w + (base + i) * 6 + o), a);
        h3p[q][o] = a;
    }
    __syncthreads();
    if (t < 6) {
        float a = o3b[t];
        #pragma unroll
        for (int q = 0; q < 6; q++) a += h3p[q][t];
        out[bx * 6 + t] = a;
    }
}

extern "C" void kernel_launch(void* const* d_in, const int* in_sizes, int n_in,
                              void* d_out, int out_size)
{
    const float* nodes  = (const float*)d_in[0];
    const float* pos    = (const float*)d_in[1];
    const float* attmap = (const float*)d_in[2];
    const float* depths = (const float*)d_in[3];
    const float* c1w  = (const float*)d_in[4];
    const float* c1b  = (const float*)d_in[5];
    const float* c2w  = (const float*)d_in[6];
    const float* c2b  = (const float*)d_in[7];
    const float* lw   = (const float*)d_in[8];
    const float* lb   = (const float*)d_in[9];
    const float* dc1w = (const float*)d_in[10];
    const float* dc1b = (const float*)d_in[11];
    const float* dc2w = (const float*)d_in[12];
    const float* dc2b = (const float*)d_in[13];
    const float* dlw  = (const float*)d_in[14];
    const float* dlb  = (const float*)d_in[15];
    const float* fmw  = (const float*)d_in[16];
    const float* fmb  = (const float*)d_in[17];
    const float* lmw  = (const float*)d_in[18];
    const float* lmb  = (const float*)d_in[19];
    const float* o1w  = (const float*)d_in[20];
    const float* o1b  = (const float*)d_in[21];
    const float* o2w  = (const float*)d_in[22];
    const float* o2b  = (const float*)d_in[23];
    const float* o3w  = (const float*)d_in[24];
    const float* o3b  = (const float*)d_in[25];

    cudaFuncSetAttribute(backbone_kernel,
                         cudaFuncAttributeMaxDynamicSharedMemorySize, SMEM_BYTES);

    backbone_kernel<<<dim3(NIMG, 2), 128, SMEM_BYTES>>>(
        nodes, depths, c1w, c1b, c2w, c2b, lw, lb,
        dc1w, dc1b, dc2w, dc2b, dlw, dlb);

    // head with programmatic dependent launch (overlaps with backbone tail)
    cudaLaunchAttribute attrs[1];
    attrs[0].id = cudaLaunchAttributeProgrammaticStreamSerialization;
    attrs[0].val.programmaticStreamSerializationAllowed = 1;
    cudaLaunchConfig_t cfg = {};
    cfg.gridDim = dim3(NB);
    cfg.blockDim = dim3(768);
    cfg.dynamicSmemBytes = 0;
    cfg.stream = 0;
    cfg.attrs = attrs;
    cfg.numAttrs = 1;
    cudaLaunchKernelEx(&cfg, head_kernel, pos, attmap, fmw, fmb, lmw, lmb,
                       o1w, o1b, o2w, o2b, o3w, o3b, (float*)d_out);
}